// round 2
// baseline (speedup 1.0000x reference)
#include <cuda_runtime.h>
#include <cuda_bf16.h>

#define N_NODES 50000
#define N_EDGES 800000
#define D 128
#define GR 64  // rows of output tile per GEMM block

// Scratch (device globals: no allocation allowed in kernel_launch)
__device__ float g_upd[N_NODES * D];
__device__ int   g_deg_in[N_NODES];
__device__ int   g_deg_out[N_NODES];

// ---------------------------------------------------------------------------
// Kernel 1: zero the accumulator, init degrees to 1 (the self-loop "+1")
// ---------------------------------------------------------------------------
__global__ void init_kernel() {
    int i = blockIdx.x * blockDim.x + threadIdx.x;
    const int total4 = N_NODES * D / 4;
    if (i < total4) {
        reinterpret_cast<float4*>(g_upd)[i] = make_float4(0.f, 0.f, 0.f, 0.f);
    }
    if (i < N_NODES) {
        g_deg_in[i]  = 1;
        g_deg_out[i] = 1;
    }
}

// ---------------------------------------------------------------------------
// Kernel 2: degree histograms (int RED to L2-resident 200KB arrays)
// ---------------------------------------------------------------------------
__global__ void degree_kernel(const int2* __restrict__ edges) {
    int i = blockIdx.x * blockDim.x + threadIdx.x;
    if (i < N_EDGES) {
        int2 e = edges[i];
        atomicAdd(&g_deg_in[e.x], 1);
        atomicAdd(&g_deg_out[e.y], 1);
    }
}

// ---------------------------------------------------------------------------
// Kernel 3: weighted gather-scatter. One warp per (edge | self-loop).
// lane l handles floats [4l, 4l+4) of the 128-wide feature row.
// update[v] += x[u] / (sqrt(deg_in[u]*deg_out[v]) + 1e-10)
// Uses red.global.add.v4.f32 (sm_90+) to quarter the atomic op count.
// ---------------------------------------------------------------------------
__global__ void scatter_kernel(const int2* __restrict__ edges,
                               const float* __restrict__ x) {
    int gw   = (blockIdx.x * blockDim.x + threadIdx.x) >> 5;
    int lane = threadIdx.x & 31;
    if (gw >= N_EDGES + N_NODES) return;

    int u, v;
    if (gw < N_EDGES) {
        int2 e = edges[gw];
        u = e.x; v = e.y;
    } else {
        u = gw - N_EDGES;  // self-loop
        v = u;
    }

    // broadcast loads (all lanes same address -> single request)
    float di = (float)g_deg_in[u];
    float dv = (float)g_deg_out[v];
    float w  = 1.0f / (sqrtf(di * dv) + 1e-10f);

    float4 xv = reinterpret_cast<const float4*>(x)[u * (D / 4) + lane];
    float* dst = &g_upd[v * D + lane * 4];
    asm volatile("red.global.add.v4.f32 [%0], {%1,%2,%3,%4};"
                 :: "l"(dst), "f"(xv.x * w), "f"(xv.y * w),
                    "f"(xv.z * w), "f"(xv.w * w)
                 : "memory");
}

// ---------------------------------------------------------------------------
// Kernel 4: out = relu(U @ W^T + b)
// Block: 256 threads, 64-row x 128-col output tile.
// W staged in smem padded to 132-float rows (LDS.128 conflict-free: lane l's
// phase bank = (l*132)%32 = 4l%32, distinct within each 8-lane phase).
// Thread (warp w, lane l): rows w*8..w*8+7, cols {l, l+32, l+64, l+96}.
// Per 4-k chunk: 12 LDS.128 -> 128 FFMA (FMA-pipe bound).
// ---------------------------------------------------------------------------
#define WPAD 132
#define SMEM_BYTES (D * WPAD * 4 + GR * D * 4)

__global__ __launch_bounds__(256) void gemm_relu_kernel(
    const float* __restrict__ Wm,
    const float* __restrict__ b,
    float* __restrict__ out) {
    extern __shared__ float smem[];
    float* Ws = smem;              // [D][WPAD]
    float* Us = smem + D * WPAD;   // [GR][D]

    int tid  = threadIdx.x;
    int lane = tid & 31;
    int warp = tid >> 5;
    int rowbase = blockIdx.x * GR;

    // Stage W: [d][k] with padded rows (16B-aligned: WPAD%4==0)
    for (int t = tid; t < D * D / 4; t += 256) {
        int d = (t * 4) / D;
        int k = (t * 4) % D;
        float4 wv = reinterpret_cast<const float4*>(Wm)[t];
        *reinterpret_cast<float4*>(&Ws[d * WPAD + k]) = wv;
    }
    // Stage U tile
    for (int t = tid; t < GR * D / 4; t += 256) {
        int r = (t * 4) / D;
        int k = (t * 4) % D;
        int row = rowbase + r;
        float4 uv = (row < N_NODES)
            ? reinterpret_cast<const float4*>(g_upd)[row * (D / 4) + (k >> 2)]
            : make_float4(0.f, 0.f, 0.f, 0.f);
        *reinterpret_cast<float4*>(&Us[r * D + k]) = uv;
    }
    __syncthreads();

    float bj[4];
#pragma unroll
    for (int j = 0; j < 4; j++) bj[j] = __ldg(&b[lane + 32 * j]);

    float acc[8][4];
#pragma unroll
    for (int i = 0; i < 8; i++)
#pragma unroll
        for (int j = 0; j < 4; j++) acc[i][j] = bj[j];

    int r0 = warp * 8;
#pragma unroll
    for (int k = 0; k < D; k += 4) {
        float4 wv[4];
#pragma unroll
        for (int j = 0; j < 4; j++)
            wv[j] = *reinterpret_cast<const float4*>(&Ws[(lane + 32 * j) * WPAD + k]);
#pragma unroll
        for (int i = 0; i < 8; i++) {
            float4 uv = *reinterpret_cast<const float4*>(&Us[(r0 + i) * D + k]);
#pragma unroll
            for (int j = 0; j < 4; j++) {
                acc[i][j] += uv.x * wv[j].x;
                acc[i][j] += uv.y * wv[j].y;
                acc[i][j] += uv.z * wv[j].z;
                acc[i][j] += uv.w * wv[j].w;
            }
        }
    }

#pragma unroll
    for (int i = 0; i < 8; i++) {
        int row = rowbase + r0 + i;
        if (row < N_NODES) {
#pragma unroll
            for (int j = 0; j < 4; j++)
                out[row * D + lane + 32 * j] = fmaxf(acc[i][j], 0.0f);
        }
    }
}

// ---------------------------------------------------------------------------
// Launch
// Inputs (metadata order): edge_list [800000,2] i32, x [50000,128] f32,
//                          W [128,128] f32, b [128] f32. Output f32 [50000,128].
// ---------------------------------------------------------------------------
extern "C" void kernel_launch(void* const* d_in, const int* in_sizes, int n_in,
                              void* d_out, int out_size) {
    const int2*  edges = (const int2*) d_in[0];
    const float* x     = (const float*)d_in[1];
    const float* Wm    = (const float*)d_in[2];
    const float* b     = (const float*)d_in[3];
    float* out = (float*)d_out;

    // opt in to >48KB dynamic smem (immediate API, not a stream op; capture-safe)
    static bool attr_done = false;
    if (!attr_done) {
        cudaFuncSetAttribute(gemm_relu_kernel,
                             cudaFuncAttributeMaxDynamicSharedMemorySize,
                             SMEM_BYTES);
        attr_done = true;
    }

    {   // init: max(1.6M float4, 50000) indices
        int total = N_NODES * D / 4;
        init_kernel<<<(total + 255) / 256, 256>>>();
    }
    degree_kernel<<<(N_EDGES + 255) / 256, 256>>>(edges);
    {
        long long warps = (long long)N_EDGES + N_NODES;
        int blocks = (int)((warps + 7) / 8);  // 8 warps / 256-thread block
        scatter_kernel<<<blocks, 256>>>(edges, x);
    }
    {
        int blocks = (N_NODES + GR - 1) / GR;
        gemm_relu_kernel<<<blocks, 256, SMEM_BYTES>>>(Wm, b, out);
    }
}